// round 10
// baseline (speedup 1.0000x reference)
#include <cuda_runtime.h>
#include <math.h>

#define BB 4
#define NN 4096
#define DKK 64
#define MT 12                       // Fourier modes (truncation rel_err ~5e-6)
#define THALF 8.0
#define OMEGA1 0.39269908169872414f // pi/8
#define TILE 64
#define NBLK 256                    // BB*NN/TILE
#define FSTR 132                    // per-mode row: [0:64) C, [64:128) S, cc, ss, pad2
#define FLEN (MT*FSTR)              // 1584

typedef unsigned long long ull;

struct CoefArg { float a[MT]; };

__device__ __align__(16) float g_Q[BB*NN];
__device__ __align__(16) float g_part[(size_t)NBLK*FLEN];   // x-features per tile
__device__ __align__(16) float g_featX[BB*FLEN];            // x-features per batch
__device__ __align__(16) float g_feat[BB*FLEN];             // a_m-scaled V-features

// ---- packed f32x2 helpers (Blackwell dual-lane FFMA, PTX-only) ----
__device__ __forceinline__ ull pk2(float lo, float hi) {
    ull r; asm("mov.b64 %0, {%1,%2};" : "=l"(r) : "f"(lo), "f"(hi)); return r;
}
__device__ __forceinline__ void upk2(ull v, float& lo, float& hi) {
    asm("mov.b64 {%0,%1}, %2;" : "=f"(lo), "=f"(hi) : "l"(v));
}
__device__ __forceinline__ ull fma2(ull a, ull b, ull c) {
    ull r; asm("fma.rn.f32x2 %0, %1, %2, %3;" : "=l"(r) : "l"(a), "l"(b), "l"(c)); return r;
}
__device__ __forceinline__ ull add2(ull a, ull b) {
    ull r; asm("add.rn.f32x2 %0, %1, %2;" : "=l"(r) : "l"(a), "l"(b)); return r;
}

// ---------------------------------------------------------------------------
// K1: per-tile Q,K + Fourier features of x (V-GEMM commuted out).
// grid=256, block=256, smem ~24KB.
// ---------------------------------------------------------------------------
__global__ __launch_bounds__(256) void k_main(
    const float* __restrict__ x, const float* __restrict__ wq,
    const float* __restrict__ wk)
{
    extern __shared__ float sm[];
    float* xs  = sm;                 // 64*68 = 4352
    float* cs2 = xs + TILE*68;       // 12*132 = 1584 (interleaved c,s per mode)
    float* wqs = cs2 + MT*FSTR;      // 64
    float* wks = wqs + 64;           // 64

    const int t = threadIdx.x;
    const int blk = blockIdx.x;
    const float* xt = x + (size_t)blk * TILE * DKK;

    // -- Phase A: stage x (float4, 4/thread) --
    {
        const float4* xt4 = (const float4*)xt;
        #pragma unroll
        for (int it = 0; it < 4; it++) {
            int f = it*256 + t;
            float4 v = xt4[f];
            *(float4*)&xs[(f >> 4)*68 + (f & 15)*4] = v;
        }
        if (t < DKK) { wqs[t] = wq[t]; wks[t] = wk[t]; }
    }
    __syncthreads();

    const int j = t >> 2, p = t & 3;

    // -- Phase B: Q,K scalars (quad-split) + mode table (4 lanes x 3 modes) --
    {
        float q = 0.f, k = 0.f;
        const float* xr = xs + j*68 + p*16;
        #pragma unroll
        for (int d = 0; d < 16; d++) {
            q = fmaf(xr[d], wqs[p*16 + d], q);
            k = fmaf(xr[d], wks[p*16 + d], k);
        }
        q += __shfl_xor_sync(0xffffffffu, q, 1);
        q += __shfl_xor_sync(0xffffffffu, q, 2);
        k += __shfl_xor_sync(0xffffffffu, k, 1);
        k += __shfl_xor_sync(0xffffffffu, k, 2);
        if (p == 0) g_Q[(size_t)blk*TILE + j] = q;
        float th = OMEGA1 * k;
        float s1, c1; __sincosf(th, &s1, &c1);
        float s0, c0; __sincosf(3.f * (float)p * th, &s0, &c0);
        #pragma unroll
        for (int mi = 0; mi < 3; mi++) {
            int m = 3*p + mi;
            *(float2*)&cs2[m*FSTR + 2*j] = make_float2(c0, s0);
            float cn = c0*c1 - s0*s1;
            s0 = fmaf(s0, c1, c0*s1);
            c0 = cn;
        }
    }
    __syncthreads();

    // -- Phase D: x-feature rank update. t<192: (d4 = t&15, m = t>>4) --
    if (t < 16*MT) {
        const int d4 = t & 15, m = t >> 4;
        float aC0=0,aC1=0,aC2=0,aC3=0, aS0=0,aS1=0,aS2=0,aS3=0;
        float aCC=0.f, aSS=0.f;
        #pragma unroll 8
        for (int jt = 0; jt < TILE; jt++) {
            float4 v = *(const float4*)&xs[jt*68 + d4*4];
            float2 cspair = *(const float2*)&cs2[m*FSTR + 2*jt];  // broadcast
            aC0 = fmaf(cspair.x, v.x, aC0); aC1 = fmaf(cspair.x, v.y, aC1);
            aC2 = fmaf(cspair.x, v.z, aC2); aC3 = fmaf(cspair.x, v.w, aC3);
            aS0 = fmaf(cspair.y, v.x, aS0); aS1 = fmaf(cspair.y, v.y, aS1);
            aS2 = fmaf(cspair.y, v.z, aS2); aS3 = fmaf(cspair.y, v.w, aS3);
            aCC += cspair.x; aSS += cspair.y;
        }
        float* bse = g_part + (size_t)blk * FLEN + m*FSTR;
        *(float4*)&bse[d4*4]      = make_float4(aC0, aC1, aC2, aC3);
        *(float4*)&bse[64 + d4*4] = make_float4(aS0, aS1, aS2, aS3);
        if (d4 == 0) { bse[128] = aCC; bse[129] = aSS; }
    }
}

// ---------------------------------------------------------------------------
// K2: reduce 64 tile-partials per batch (deterministic)
// ---------------------------------------------------------------------------
__global__ __launch_bounds__(256) void k_red()
{
    int f = blockIdx.x * 256 + threadIdx.x;
    int b = blockIdx.y;
    if (f >= FLEN) return;
    const float* src = g_part + (size_t)b*64*FLEN + f;
    float s = 0.f;
    #pragma unroll 16
    for (int tb = 0; tb < 64; tb++)
        s += src[(size_t)tb*FLEN];
    g_featX[b*FLEN + f] = s;
}

// ---------------------------------------------------------------------------
// K2b: tiny GEMM + a_m folding. grid=(4 batches, 3 mode-groups), block=256.
// ---------------------------------------------------------------------------
__global__ __launch_bounds__(256) void k_gemm(
    const float* __restrict__ Wv, const float* __restrict__ bv, CoefArg ca)
{
    extern __shared__ float sm[];
    float* Wvs = sm;                 // 64*65 = 4160 (padded rows)
    float* Xms = Wvs + 64*65;        // 4*132 = 528
    float* bvs = Xms + 4*FSTR;       // 64

    const int t = threadIdx.x;
    const int b = blockIdx.x;
    const int mg = blockIdx.y;       // modes 4*mg .. 4*mg+3

    #pragma unroll
    for (int it = 0; it < 16; it++) {
        int i = it*256 + t;          // i = e*64 + d
        Wvs[(i >> 6)*65 + (i & 63)] = Wv[i];
    }
    if (t < DKK) bvs[t] = bv[t];
    if (t < FSTR) {
        #pragma unroll
        for (int mm = 0; mm < 4; mm++)
            Xms[mm*FSTR + t] = g_featX[b*FLEN + (mg*4 + mm)*FSTR + t];
    }
    __syncthreads();

    const int h = t & 1, k2 = (t >> 1) & 1, e = t >> 2;

    #pragma unroll
    for (int mm = 0; mm < 4; mm++) {
        int m = mg*4 + mm;
        float am = ca.a[m];
        const float* xv = Xms + mm*FSTR + k2*64 + h*32;
        const float* wr = Wvs + e*65 + h*32;
        float acc = 0.f;
        #pragma unroll
        for (int d = 0; d < 32; d++)
            acc = fmaf(xv[d], wr[d], acc);
        acc += __shfl_xor_sync(0xffffffffu, acc, 1);
        if (h == 0) {
            float sc = Xms[mm*FSTR + 128 + k2];   // cc for C, ss for S
            g_feat[b*FLEN + m*FSTR + k2*64 + e] = am * fmaf(sc, bvs[e], acc);
        }
        if (t < 2)
            g_feat[b*FLEN + m*FSTR + 128 + t] = am * Xms[mm*FSTR + 128 + t];
    }
}

// ---------------------------------------------------------------------------
// K3: per-token output + residual + LayerNorm. No smem; f32x2 packed FMA.
// grid=1024, block=256, 8 CTAs/SM -> single wave.
// ---------------------------------------------------------------------------
__global__ __launch_bounds__(256, 8) void k_out(
    const float* __restrict__ x, const float* __restrict__ gamma,
    const float* __restrict__ beta, float* __restrict__ out)
{
    const int t = threadIdx.x;
    const int blk = blockIdx.x;
    const int b = blk >> 8;

    const float* gf = g_feat + b*FLEN;
    const int p = t & 15;
    const size_t tok = (size_t)blk*16 + (t >> 4);

    float q = g_Q[tok];
    float th = OMEGA1 * q;
    float s1, c1; __sincosf(th, &s1, &c1);
    float s2, c2; __sincosf(2.f*th, &s2, &c2);

    float cA = 1.f, sA = 0.f;     // even modes, step 2theta
    float cB = c1,  sB = s1;      // odd modes

    ull nAlo = 0, nAhi = 0, nBlo = 0, nBhi = 0;   // (0.0f,0.0f) packed
    ull dA = 0, dB = 0;                            // (den_c, den_s) pairs

    #pragma unroll
    for (int h = 0; h < MT/2; h++) {
        {   // even mode 2h
            const float* bse = gf + (2*h)*FSTR;
            ull dd = __ldg((const ull*)(bse + 128));
            dA = fma2(pk2(cA, sA), dd, dA);
            ulonglong2 C = __ldg((const ulonglong2*)(bse + p*4));
            ulonglong2 S = __ldg((const ulonglong2*)(bse + 64 + p*4));
            ull wc = pk2(cA, cA), ws = pk2(sA, sA);
            nAlo = fma2(wc, C.x, fma2(ws, S.x, nAlo));
            nAhi = fma2(wc, C.y, fma2(ws, S.y, nAhi));
            float cn = cA*c2 - sA*s2;
            sA = fmaf(sA, c2, cA*s2);
            cA = cn;
        }
        {   // odd mode 2h+1
            const float* bse = gf + (2*h+1)*FSTR;
            ull dd = __ldg((const ull*)(bse + 128));
            dB = fma2(pk2(cB, sB), dd, dB);
            ulonglong2 C = __ldg((const ulonglong2*)(bse + p*4));
            ulonglong2 S = __ldg((const ulonglong2*)(bse + 64 + p*4));
            ull wc = pk2(cB, cB), ws = pk2(sB, sB);
            nBlo = fma2(wc, C.x, fma2(ws, S.x, nBlo));
            nBhi = fma2(wc, C.y, fma2(ws, S.y, nBhi));
            float cn = cB*c2 - sB*s2;
            sB = fmaf(sB, c2, cB*s2);
            cB = cn;
        }
    }

    float dAc, dAs, dBc, dBs;
    upk2(dA, dAc, dAs); upk2(dB, dBc, dBs);
    float den = (dAc + dAs) + (dBc + dBs);

    ull nlo = add2(nAlo, nBlo), nhi = add2(nAhi, nBhi);
    float4 num;
    upk2(nlo, num.x, num.y);
    upk2(nhi, num.z, num.w);

    float4 xr = *(const float4*)(x + tok*DKK + p*4);
    float invden = 1.f / den;
    num.x = fmaf(num.x, invden, xr.x);
    num.y = fmaf(num.y, invden, xr.y);
    num.z = fmaf(num.z, invden, xr.z);
    num.w = fmaf(num.w, invden, xr.w);

    float psum = num.x + num.y + num.z + num.w;
    psum += __shfl_xor_sync(0xffffffffu, psum, 1);
    psum += __shfl_xor_sync(0xffffffffu, psum, 2);
    psum += __shfl_xor_sync(0xffffffffu, psum, 4);
    psum += __shfl_xor_sync(0xffffffffu, psum, 8);
    float mu = psum * (1.f/64.f);

    float dx = num.x - mu, dy = num.y - mu, dz = num.z - mu, dw = num.w - mu;
    float pvar = dx*dx + dy*dy + dz*dz + dw*dw;
    pvar += __shfl_xor_sync(0xffffffffu, pvar, 1);
    pvar += __shfl_xor_sync(0xffffffffu, pvar, 2);
    pvar += __shfl_xor_sync(0xffffffffu, pvar, 4);
    pvar += __shfl_xor_sync(0xffffffffu, pvar, 8);
    float rstd = rsqrtf(pvar*(1.f/64.f) + 1e-5f);

    float4 g4 = __ldg((const float4*)(gamma + p*4));
    float4 b4 = __ldg((const float4*)(beta  + p*4));
    float4 o;
    o.x = dx * rstd * g4.x + b4.x;
    o.y = dy * rstd * g4.y + b4.y;
    o.z = dz * rstd * g4.z + b4.z;
    o.w = dw * rstd * g4.w + b4.w;
    *(float4*)(out + tok*DKK + p*4) = o;
}

// ---------------------------------------------------------------------------
extern "C" void kernel_launch(void* const* d_in, const int* in_sizes, int n_in,
                              void* d_out, int out_size)
{
    const float* x     = (const float*)d_in[0];
    const float* Wv    = (const float*)d_in[1];
    const float* bv    = (const float*)d_in[2];
    const float* wq    = (const float*)d_in[3];
    const float* wk    = (const float*)d_in[4];
    const float* gamma = (const float*)d_in[5];
    const float* beta  = (const float*)d_in[6];
    float* out = (float*)d_out;

    // Fourier cosine coefficients of g(t)=exp(exp(-t^2)/8), host double precision
    CoefArg ca;
    {
        const int P = 8192;
        const double T = THALF, L = 2.0*T;
        for (int m = 0; m < MT; m++) {
            double wm = 3.14159265358979323846 * (double)m / T;
            double sum = 0.0;
            for (int ip = 0; ip < P; ip++) {
                double tt = -T + (ip + 0.5) * (L / P);
                sum += exp(exp(-tt*tt) * 0.125) * cos(wm * tt);
            }
            ca.a[m] = (float)(((m == 0) ? 1.0 : 2.0) * sum / (double)P);
        }
    }

    const size_t sm1 = (size_t)(TILE*68 + MT*FSTR + 2*64) * sizeof(float);
    const size_t smg = (size_t)(64*65 + 4*FSTR + 64) * sizeof(float);
    cudaFuncSetAttribute(k_main, cudaFuncAttributeMaxDynamicSharedMemorySize, (int)sm1);
    cudaFuncSetAttribute(k_gemm, cudaFuncAttributeMaxDynamicSharedMemorySize, (int)smg);

    k_main<<<NBLK, 256, sm1>>>(x, wq, wk);
    k_red<<<dim3((FLEN + 255)/256, BB), 256>>>();
    k_gemm<<<dim3(BB, MT/4), 256, smg>>>(Wv, bv, ca);
    k_out<<<1024, 256>>>(x, gamma, beta, out);
}

// round 11
// speedup vs baseline: 1.3125x; 1.3125x over previous
#include <cuda_runtime.h>
#include <math.h>

#define BB 4
#define NN 4096
#define DKK 64
#define MT 12                       // Fourier modes (truncation rel_err ~3e-6)
#define THALF 8.0
#define OMEGA1 0.39269908169872414f // pi/8
#define TILE 64
#define NBLK 256                    // BB*NN/TILE
#define FSTR 132                    // per-mode row: [0:64) C, [64:128) S, cc, ss, pad2
#define FLEN (MT*FSTR)              // 1584

typedef unsigned long long ull;

struct CoefArg { float a[MT]; };

__device__ __align__(16) float g_Q[BB*NN];
__device__ __align__(16) float g_part[(size_t)NBLK*FLEN];   // x-features per tile
__device__ __align__(16) float g_feat[BB*FLEN];             // a_m-scaled V-features

// ---- packed f32x2 helpers (Blackwell dual-lane FFMA, PTX-only) ----
__device__ __forceinline__ ull pk2(float lo, float hi) {
    ull r; asm("mov.b64 %0, {%1,%2};" : "=l"(r) : "f"(lo), "f"(hi)); return r;
}
__device__ __forceinline__ void upk2(ull v, float& lo, float& hi) {
    asm("mov.b64 {%0,%1}, %2;" : "=f"(lo), "=f"(hi) : "l"(v));
}
__device__ __forceinline__ ull fma2(ull a, ull b, ull c) {
    ull r; asm("fma.rn.f32x2 %0, %1, %2, %3;" : "=l"(r) : "l"(a), "l"(b), "l"(c)); return r;
}

// ---------------------------------------------------------------------------
// K1: per-tile Q,K + Fourier features of x (V-GEMM commuted out).
// grid=256, block=256, smem ~24KB.
// ---------------------------------------------------------------------------
__global__ __launch_bounds__(256) void k_main(
    const float* __restrict__ x, const float* __restrict__ wq,
    const float* __restrict__ wk)
{
    extern __shared__ float sm[];
    float* xs  = sm;                 // 64*68 = 4352
    float* cs2 = xs + TILE*68;       // 12*132 = 1584 (interleaved c,s per mode)
    float* wqs = cs2 + MT*FSTR;      // 64
    float* wks = wqs + 64;           // 64

    const int t = threadIdx.x;
    const int blk = blockIdx.x;
    const float* xt = x + (size_t)blk * TILE * DKK;

    // -- Phase A: stage x (float4, 4/thread) --
    {
        const float4* xt4 = (const float4*)xt;
        #pragma unroll
        for (int it = 0; it < 4; it++) {
            int f = it*256 + t;
            float4 v = xt4[f];
            *(float4*)&xs[(f >> 4)*68 + (f & 15)*4] = v;
        }
        if (t < DKK) { wqs[t] = wq[t]; wks[t] = wk[t]; }
    }
    __syncthreads();

    const int j = t >> 2, p = t & 3;

    // -- Phase B: Q,K scalars (quad-split) + mode table (4 lanes x 3 modes) --
    {
        float q = 0.f, k = 0.f;
        const float* xr = xs + j*68 + p*16;
        #pragma unroll
        for (int d = 0; d < 16; d++) {
            q = fmaf(xr[d], wqs[p*16 + d], q);
            k = fmaf(xr[d], wks[p*16 + d], k);
        }
        q += __shfl_xor_sync(0xffffffffu, q, 1);
        q += __shfl_xor_sync(0xffffffffu, q, 2);
        k += __shfl_xor_sync(0xffffffffu, k, 1);
        k += __shfl_xor_sync(0xffffffffu, k, 2);
        if (p == 0) g_Q[(size_t)blk*TILE + j] = q;
        float th = OMEGA1 * k;
        float s1, c1; __sincosf(th, &s1, &c1);
        float s0, c0; __sincosf(3.f * (float)p * th, &s0, &c0);
        #pragma unroll
        for (int mi = 0; mi < 3; mi++) {
            int m = 3*p + mi;
            *(float2*)&cs2[m*FSTR + 2*j] = make_float2(c0, s0);
            float cn = c0*c1 - s0*s1;
            s0 = fmaf(s0, c1, c0*s1);
            c0 = cn;
        }
    }
    __syncthreads();

    // -- Phase D: x-feature rank update. t<192: (d4 = t&15, m = t>>4) --
    if (t < 16*MT) {
        const int d4 = t & 15, m = t >> 4;
        float aC0=0,aC1=0,aC2=0,aC3=0, aS0=0,aS1=0,aS2=0,aS3=0;
        float aCC=0.f, aSS=0.f;
        #pragma unroll 8
        for (int jt = 0; jt < TILE; jt++) {
            float4 v = *(const float4*)&xs[jt*68 + d4*4];
            float2 cspair = *(const float2*)&cs2[m*FSTR + 2*jt];  // broadcast
            aC0 = fmaf(cspair.x, v.x, aC0); aC1 = fmaf(cspair.x, v.y, aC1);
            aC2 = fmaf(cspair.x, v.z, aC2); aC3 = fmaf(cspair.x, v.w, aC3);
            aS0 = fmaf(cspair.y, v.x, aS0); aS1 = fmaf(cspair.y, v.y, aS1);
            aS2 = fmaf(cspair.y, v.z, aS2); aS3 = fmaf(cspair.y, v.w, aS3);
            aCC += cspair.x; aSS += cspair.y;
        }
        float* bse = g_part + (size_t)blk * FLEN + m*FSTR;
        *(float4*)&bse[d4*4]      = make_float4(aC0, aC1, aC2, aC3);
        *(float4*)&bse[64 + d4*4] = make_float4(aS0, aS1, aS2, aS3);
        if (d4 == 0) { bse[128] = aCC; bse[129] = aSS; }
    }
}

// ---------------------------------------------------------------------------
// K2: fused reduce + Wv-GEMM + a_m folding.
// grid=(BB, MT) = 48 CTAs, block=256. Each CTA owns one (batch, mode) row:
//   Xrow = sum over 64 tile-partials; C = a_m*(Xc @ Wv^T + cc*bv), etc.
// ---------------------------------------------------------------------------
__global__ __launch_bounds__(256) void k_rg(
    const float* __restrict__ Wv, const float* __restrict__ bv, CoefArg ca)
{
    extern __shared__ float sm[];
    float* Wvs = sm;                 // 64*65 = 4160 (padded rows)
    float* Xm  = Wvs + 64*65;        // 132
    float* bvs = Xm + FSTR;          // 64

    const int t = threadIdx.x;
    const int b = blockIdx.x;
    const int m = blockIdx.y;
    const float am = ca.a[m];

    // stage Wv + bv
    #pragma unroll
    for (int it = 0; it < 16; it++) {
        int i = it*256 + t;          // i = e*64 + d
        Wvs[(i >> 6)*65 + (i & 63)] = Wv[i];
    }
    if (t < DKK) bvs[t] = bv[t];

    // reduce this mode-row over 64 tiles (threads 0..131, coalesced per f)
    if (t < FSTR) {
        const float* src = g_part + ((size_t)b*64)*FLEN + m*FSTR + t;
        float s = 0.f;
        #pragma unroll 16
        for (int tb = 0; tb < 64; tb++)
            s += src[(size_t)tb*FLEN];
        Xm[t] = s;
    }
    __syncthreads();

    // GEMM: thread (h = t&1 d-half, k2 = (t>>1)&1 C/S, e = t>>2)
    const int h = t & 1, k2 = (t >> 1) & 1, e = t >> 2;
    {
        const float* xv = Xm + k2*64 + h*32;
        const float* wr = Wvs + e*65 + h*32;
        float acc = 0.f;
        #pragma unroll
        for (int d = 0; d < 32; d++)
            acc = fmaf(xv[d], wr[d], acc);
        acc += __shfl_xor_sync(0xffffffffu, acc, 1);
        if (h == 0) {
            float sc = Xm[128 + k2];   // cc for C, ss for S
            g_feat[b*FLEN + m*FSTR + k2*64 + e] = am * fmaf(sc, bvs[e], acc);
        }
        if (t < 2)
            g_feat[b*FLEN + m*FSTR + 128 + t] = am * Xm[128 + t];
    }
}

// ---------------------------------------------------------------------------
// K3: per-token output + residual + LayerNorm.
// grid=512, block=256. Each thread owns 2 tokens x 4 dims; the C/S/dd loads
// per mode are shared across both tokens (4x fewer LDG than 1-token layout).
// ---------------------------------------------------------------------------
__global__ __launch_bounds__(256) void k_out(
    const float* __restrict__ x, const float* __restrict__ gamma,
    const float* __restrict__ beta, float* __restrict__ out)
{
    const int t = threadIdx.x;
    const int blk = blockIdx.x;          // 512 blocks, 32 tokens each
    const int b = blk >> 7;              // 128 blocks per batch

    const int lane = t & 31, w = t >> 5;
    const int g = lane >> 4;             // half-warp: token pair select
    const int p = lane & 15;             // 4-dim slice
    const size_t tok0 = (size_t)blk*32 + w*4 + g*2;   // this thread: tok0, tok0+1

    const float* gf = g_feat + b*FLEN;

    float q0 = __ldg(&g_Q[tok0]);
    float q1 = __ldg(&g_Q[tok0 + 1]);
    float sa, ca_; __sincosf(OMEGA1*q0, &sa, &ca_);
    float sb, cb_; __sincosf(OMEGA1*q1, &sb, &cb_);

    float c0 = 1.f, s0 = 0.f;            // token0 chain
    float c1 = 1.f, s1 = 0.f;            // token1 chain

    ull n0lo = 0, n0hi = 0, n1lo = 0, n1hi = 0;
    ull d0 = 0, d1 = 0;

    #pragma unroll
    for (int m = 0; m < MT; m++) {
        const float* bse = gf + m*FSTR;
        ull dd = __ldg((const ull*)(bse + 128));
        ulonglong2 C = __ldg((const ulonglong2*)(bse + p*4));
        ulonglong2 S = __ldg((const ulonglong2*)(bse + 64 + p*4));
        // token 0
        {
            ull wc = pk2(c0, c0), ws = pk2(s0, s0);
            n0lo = fma2(wc, C.x, fma2(ws, S.x, n0lo));
            n0hi = fma2(wc, C.y, fma2(ws, S.y, n0hi));
            d0 = fma2(pk2(c0, s0), dd, d0);
            float cn = fmaf(c0, ca_, -(s0*sa));
            s0 = fmaf(s0, ca_, c0*sa);
            c0 = cn;
        }
        // token 1
        {
            ull wc = pk2(c1, c1), ws = pk2(s1, s1);
            n1lo = fma2(wc, C.x, fma2(ws, S.x, n1lo));
            n1hi = fma2(wc, C.y, fma2(ws, S.y, n1hi));
            d1 = fma2(pk2(c1, s1), dd, d1);
            float cn = fmaf(c1, cb_, -(s1*sb));
            s1 = fmaf(s1, cb_, c1*sb);
            c1 = cn;
        }
    }

    float4 g4 = __ldg((const float4*)(gamma + p*4));
    float4 b4 = __ldg((const float4*)(beta  + p*4));

    #pragma unroll
    for (int i = 0; i < 2; i++) {
        size_t tok = tok0 + i;
        ull nlo = i ? n1lo : n0lo;
        ull nhi = i ? n1hi : n0hi;
        ull dpk = i ? d1 : d0;
        float dc, ds; upk2(dpk, dc, ds);
        float den = dc + ds;
        float4 num;
        upk2(nlo, num.x, num.y);
        upk2(nhi, num.z, num.w);

        float4 xr = *(const float4*)(x + tok*DKK + p*4);
        float invden = 1.f / den;
        num.x = fmaf(num.x, invden, xr.x);
        num.y = fmaf(num.y, invden, xr.y);
        num.z = fmaf(num.z, invden, xr.z);
        num.w = fmaf(num.w, invden, xr.w);

        float psum = num.x + num.y + num.z + num.w;
        psum += __shfl_xor_sync(0xffffffffu, psum, 1);
        psum += __shfl_xor_sync(0xffffffffu, psum, 2);
        psum += __shfl_xor_sync(0xffffffffu, psum, 4);
        psum += __shfl_xor_sync(0xffffffffu, psum, 8);
        float mu = psum * (1.f/64.f);

        float dx = num.x - mu, dy = num.y - mu, dz = num.z - mu, dw = num.w - mu;
        float pvar = dx*dx + dy*dy + dz*dz + dw*dw;
        pvar += __shfl_xor_sync(0xffffffffu, pvar, 1);
        pvar += __shfl_xor_sync(0xffffffffu, pvar, 2);
        pvar += __shfl_xor_sync(0xffffffffu, pvar, 4);
        pvar += __shfl_xor_sync(0xffffffffu, pvar, 8);
        float rstd = rsqrtf(pvar*(1.f/64.f) + 1e-5f);

        float4 o;
        o.x = dx * rstd * g4.x + b4.x;
        o.y = dy * rstd * g4.y + b4.y;
        o.z = dz * rstd * g4.z + b4.z;
        o.w = dw * rstd * g4.w + b4.w;
        *(float4*)(out + tok*DKK + p*4) = o;
    }
}

// ---------------------------------------------------------------------------
extern "C" void kernel_launch(void* const* d_in, const int* in_sizes, int n_in,
                              void* d_out, int out_size)
{
    const float* x     = (const float*)d_in[0];
    const float* Wv    = (const float*)d_in[1];
    const float* bv    = (const float*)d_in[2];
    const float* wq    = (const float*)d_in[3];
    const float* wk    = (const float*)d_in[4];
    const float* gamma = (const float*)d_in[5];
    const float* beta  = (const float*)d_in[6];
    float* out = (float*)d_out;

    // Fourier cosine coefficients of g(t)=exp(exp(-t^2)/8), host double precision
    CoefArg ca;
    {
        const int P = 8192;
        const double T = THALF, L = 2.0*T;
        for (int m = 0; m < MT; m++) {
            double wm = 3.14159265358979323846 * (double)m / T;
            double sum = 0.0;
            for (int ip = 0; ip < P; ip++) {
                double tt = -T + (ip + 0.5) * (L / P);
                sum += exp(exp(-tt*tt) * 0.125) * cos(wm * tt);
            }
            ca.a[m] = (float)(((m == 0) ? 1.0 : 2.0) * sum / (double)P);
        }
    }

    const size_t sm1 = (size_t)(TILE*68 + MT*FSTR + 2*64) * sizeof(float);
    const size_t smg = (size_t)(64*65 + FSTR + 64) * sizeof(float);
    cudaFuncSetAttribute(k_main, cudaFuncAttributeMaxDynamicSharedMemorySize, (int)sm1);
    cudaFuncSetAttribute(k_rg,   cudaFuncAttributeMaxDynamicSharedMemorySize, (int)smg);

    k_main<<<NBLK, 256, sm1>>>(x, wq, wk);
    k_rg<<<dim3(BB, MT), 256, smg>>>(Wv, bv, ca);
    k_out<<<512, 256>>>(x, gamma, beta, out);
}